// round 3
// baseline (speedup 1.0000x reference)
#include <cuda_runtime.h>
#include <cuda_bf16.h>
#include <math.h>

// ---------------------------------------------------------------------------
// MP_Layer: GNN message-passing layer, fp32 baseline.
//   B=16, N=128, D=S=128, MP_INT=UP_INT=256.
// Pipeline:
//   K_pre : Pi_a/Pj_a/Pi_m/Pj_m/Pu = nodes @ W1x[slice]      (tiny GEMMs)
//   K_edge: per (b,p) tile of 128 edges:
//             H1 = relu(E @ W1a[256:384] + Pi_a[q] + Pj_a[p] + b1a)
//             NE = relu(H1 @ W2a + b2a) * mask
//             edges_out = BN_e(NE)
//             H2 = relu(NE @ W1m[256:384] + Pi_m[q] + Pj_m[p] + b1m)
//             MSG = relu(H2 @ W2m + b2m) * mask
//             agg[b,p] = sum_q MSG            (in-block reduction, no atomics)
//   K_node: s = relu(relu(Pu + agg @ W1u[128:256] + b1u) @ W2u + b2u)
//           nodes_out = BN_n(s)
// ---------------------------------------------------------------------------

#define EPSBN 1e-3f

static const int Bb = 16;
static const int Nn = 128;
static const int Dd = 128;

// scratch (device globals; no allocation allowed)
__device__ __align__(16) float g_Pi_a[2048 * 256];
__device__ __align__(16) float g_Pj_a[2048 * 256];
__device__ __align__(16) float g_Pi_m[2048 * 256];
__device__ __align__(16) float g_Pj_m[2048 * 256];
__device__ __align__(16) float g_Pu [2048 * 256];
__device__ __align__(16) float g_agg[2048 * 128];

// XOR swizzle for transposed activation buffers: element (a=k, b=row)
// bank = (b ^ (((a>>3)&3)<<3)) mod 32 spreads column-stores across banks.
__device__ __forceinline__ int SWZ(int a, int b) {
    return a * 128 + (b ^ (((a >> 3) & 3) << 3));
}

// ---------------------------------------------------------------------------
// Generic 128xNcolsxK GEMM tile: C[128][128] (one 128-col slab),
// A^T in swizzled smem, W streamed from global via sW chunks.
// Each thread owns an 8x8 micro-tile: rows row0..row0+7, cols col0..col0+7.
// ---------------------------------------------------------------------------
__device__ __forceinline__ void gemm_tile(
    const float* __restrict__ sA,      // swizzled A^T, K x 128
    float* __restrict__ sW,            // [32][132] staging
    const float* __restrict__ gW0,     // global W, already offset to (row0=0, col=ncb)
    int ldw, int K,
    int tid, int row0, int col0,
    float (&acc)[8][8])
{
    for (int kb = 0; kb < K; kb += 32) {
        __syncthreads();
        // stage 32x128 weight chunk (1024 float4, 4 per thread, coalesced)
        #pragma unroll
        for (int i = 0; i < 4; i++) {
            int f4 = tid + (i << 8);
            int rr = f4 >> 5;
            int cc = (f4 & 31) << 2;
            *(float4*)(sW + rr * 132 + cc) =
                *(const float4*)(gW0 + (size_t)(kb + rr) * ldw + cc);
        }
        __syncthreads();
        #pragma unroll 4
        for (int kk = 0; kk < 32; kk++) {
            int k = kb + kk;
            int xk = ((k >> 3) & 3) << 3;
            const float4* ap = (const float4*)(sA + k * 128 + (row0 ^ xk));
            float4 a0 = ap[0], a1 = ap[1];
            const float4* bp = (const float4*)(sW + kk * 132 + col0);
            float4 b0 = bp[0], b1 = bp[1];
            float av[8] = {a0.x, a0.y, a0.z, a0.w, a1.x, a1.y, a1.z, a1.w};
            float bv[8] = {b0.x, b0.y, b0.z, b0.w, b1.x, b1.y, b1.z, b1.w};
            #pragma unroll
            for (int i = 0; i < 8; i++)
                #pragma unroll
                for (int j = 0; j < 8; j++)
                    acc[i][j] += av[i] * bv[j];
        }
    }
}

// store this thread's 8x8 (already activated) into swizzled dst at columns
// c = ncb+col0+j, rows row0..row0+7
__device__ __forceinline__ void store_tileT(
    float* __restrict__ sDst, int ncb, int row0, int col0, const float (&v)[8][8])
{
    #pragma unroll
    for (int j = 0; j < 8; j++) {
        int c  = ncb + col0 + j;
        int xc = ((c >> 3) & 3) << 3;
        float* d = sDst + c * 128 + (row0 ^ xc);
        float4 lo = make_float4(v[0][j], v[1][j], v[2][j], v[3][j]);
        float4 hi = make_float4(v[4][j], v[5][j], v[6][j], v[7][j]);
        *(float4*)(d)     = lo;
        *(float4*)(d + 4) = hi;
    }
}

// ---------------------------------------------------------------------------
// Kernel A: node precompute. Block = 16 node rows.
// ---------------------------------------------------------------------------
__global__ __launch_bounds__(256) void precompute_kernel(
    const float* __restrict__ nodes,
    const float* __restrict__ W1a,
    const float* __restrict__ W1m,
    const float* __restrict__ W1u)
{
    __shared__ float sX[16 * 128];
    int row0 = blockIdx.x * 16;
    int tid = threadIdx.x;
    for (int idx = tid; idx < 2048; idx += 256)
        sX[idx] = nodes[(size_t)row0 * 128 + idx];
    __syncthreads();

    const float* Ws[5] = {W1a, W1a + 128 * 256, W1m, W1m + 128 * 256, W1u};
    float* Os[5] = {g_Pi_a, g_Pj_a, g_Pi_m, g_Pj_m, g_Pu};

    #pragma unroll 1
    for (int m = 0; m < 5; m++) {
        const float* W = Ws[m] + tid;   // col = tid (0..255)
        float a[16];
        #pragma unroll
        for (int r = 0; r < 16; r++) a[r] = 0.f;
        #pragma unroll 2
        for (int kb = 0; kb < 128; kb += 4) {
            float w0 = W[(size_t)(kb + 0) * 256];
            float w1 = W[(size_t)(kb + 1) * 256];
            float w2 = W[(size_t)(kb + 2) * 256];
            float w3 = W[(size_t)(kb + 3) * 256];
            #pragma unroll
            for (int r = 0; r < 16; r++) {
                float4 xv = *(const float4*)(sX + r * 128 + kb);
                a[r] += xv.x * w0 + xv.y * w1 + xv.z * w2 + xv.w * w3;
            }
        }
        float* O = Os[m] + (size_t)row0 * 256 + tid;
        #pragma unroll
        for (int r = 0; r < 16; r++) O[(size_t)r * 256] = a[r];
    }
}

// ---------------------------------------------------------------------------
// Kernel B: fused edge pipeline. Block = one (b, p) row of 128 edges.
// smem: sE (swz 128x128) | sH (swz 256x128) | sW [32][132] (alias sRed) | sMask[128]
// ---------------------------------------------------------------------------
#define SM_E 0
#define SM_H 16384
#define SM_W 49152
#define SM_M 53376
#define SMEM_B_FLOATS 53504  // 214016 bytes

__global__ __launch_bounds__(256, 1) void edge_kernel(
    const float* __restrict__ edges, const float* __restrict__ mask,
    const float* __restrict__ W1a, const float* __restrict__ b1a,
    const float* __restrict__ W2a, const float* __restrict__ b2a,
    const float* __restrict__ W1m, const float* __restrict__ b1m,
    const float* __restrict__ W2m, const float* __restrict__ b2m,
    const float* __restrict__ gamma_e, const float* __restrict__ beta_e,
    const float* __restrict__ mean_e,  const float* __restrict__ var_e,
    float* __restrict__ edges_out)
{
    extern __shared__ float sm[];
    float* sE = sm + SM_E;
    float* sH = sm + SM_H;
    float* sW = sm + SM_W;
    float* sMask = sm + SM_M;
    float* sRed = sW;  // alias (used only after last GEMM, with sync)

    int p  = blockIdx.x;
    int bb = blockIdx.y;
    int tid = threadIdx.x;
    int ty = tid >> 4, tx = tid & 15;
    int row0 = ty * 8, col0 = tx * 8;

    // load edge tile transposed+swizzled
    const float* Eg = edges + ((size_t)bb * 16384 + (size_t)p * 128) * 128;
    for (int idx = tid; idx < 16384; idx += 256) {
        int r = idx >> 7, k = idx & 127;
        sE[SWZ(k, r)] = Eg[idx];
    }
    if (tid < 128) sMask[tid] = mask[(size_t)bb * 16384 + p * 128 + tid];

    float acc[8][8];

    // ---- GEMM1: H1 = relu(E @ W1a_e + Pi_a[q] + Pj_a[p] + b1a) -> sH
    #pragma unroll 1
    for (int h = 0; h < 2; h++) {
        int ncb = h * 128;
        #pragma unroll
        for (int i = 0; i < 8; i++)
            #pragma unroll
            for (int j = 0; j < 8; j++) acc[i][j] = 0.f;
        gemm_tile(sE, sW, W1a + (size_t)256 * 256 + ncb, 256, 128, tid, row0, col0, acc);
        float bj[8];
        {
            const float* Pj = g_Pj_a + ((size_t)(bb * 128 + p)) * 256 + ncb + col0;
            #pragma unroll
            for (int j = 0; j < 8; j++) bj[j] = b1a[ncb + col0 + j] + Pj[j];
        }
        const float* Pi = g_Pi_a + ((size_t)bb * 128) * 256 + ncb + col0;
        #pragma unroll
        for (int i = 0; i < 8; i++) {
            const float* pir = Pi + (size_t)(row0 + i) * 256;
            float4 p0 = *(const float4*)(pir);
            float4 p1 = *(const float4*)(pir + 4);
            float pv[8] = {p0.x, p0.y, p0.z, p0.w, p1.x, p1.y, p1.z, p1.w};
            #pragma unroll
            for (int j = 0; j < 8; j++) {
                float v = acc[i][j] + pv[j] + bj[j];
                acc[i][j] = fmaxf(v, 0.f);
            }
        }
        store_tileT(sH, ncb, row0, col0, acc);
    }

    // ---- GEMM2: NE = relu(H1 @ W2a + b2a) * mask ; edges_out = BN(NE); NE -> sE
    #pragma unroll
    for (int i = 0; i < 8; i++)
        #pragma unroll
        for (int j = 0; j < 8; j++) acc[i][j] = 0.f;
    gemm_tile(sH, sW, W2a, 128, 256, tid, row0, col0, acc);
    {
        float bj[8], scl[8], shf[8];
        #pragma unroll
        for (int j = 0; j < 8; j++) {
            int c = col0 + j;
            bj[j]  = b2a[c];
            float s = gamma_e[c] * rsqrtf(var_e[c] + EPSBN);
            scl[j] = s;
            shf[j] = beta_e[c] - mean_e[c] * s;
        }
        #pragma unroll
        for (int i = 0; i < 8; i++) {
            int r = row0 + i;
            float mv = sMask[r];
            float* go = edges_out + (((size_t)bb * 16384) + (size_t)p * 128 + r) * 128 + col0;
            float ov[8];
            #pragma unroll
            for (int j = 0; j < 8; j++) {
                float v = fmaxf(acc[i][j] + bj[j], 0.f) * mv;
                acc[i][j] = v;
                ov[j] = v * scl[j] + shf[j];
            }
            *(float4*)(go)     = make_float4(ov[0], ov[1], ov[2], ov[3]);
            *(float4*)(go + 4) = make_float4(ov[4], ov[5], ov[6], ov[7]);
        }
        store_tileT(sE, 0, row0, col0, acc);
    }

    // ---- GEMM3: H2 = relu(NE @ W1m_e + Pi_m[q] + Pj_m[p] + b1m) -> sH
    #pragma unroll 1
    for (int h = 0; h < 2; h++) {
        int ncb = h * 128;
        #pragma unroll
        for (int i = 0; i < 8; i++)
            #pragma unroll
            for (int j = 0; j < 8; j++) acc[i][j] = 0.f;
        gemm_tile(sE, sW, W1m + (size_t)256 * 256 + ncb, 256, 128, tid, row0, col0, acc);
        float bj[8];
        {
            const float* Pj = g_Pj_m + ((size_t)(bb * 128 + p)) * 256 + ncb + col0;
            #pragma unroll
            for (int j = 0; j < 8; j++) bj[j] = b1m[ncb + col0 + j] + Pj[j];
        }
        const float* Pi = g_Pi_m + ((size_t)bb * 128) * 256 + ncb + col0;
        #pragma unroll
        for (int i = 0; i < 8; i++) {
            const float* pir = Pi + (size_t)(row0 + i) * 256;
            float4 p0 = *(const float4*)(pir);
            float4 p1 = *(const float4*)(pir + 4);
            float pv[8] = {p0.x, p0.y, p0.z, p0.w, p1.x, p1.y, p1.z, p1.w};
            #pragma unroll
            for (int j = 0; j < 8; j++) {
                float v = acc[i][j] + pv[j] + bj[j];
                acc[i][j] = fmaxf(v, 0.f);
            }
        }
        store_tileT(sH, ncb, row0, col0, acc);
    }

    // ---- GEMM4: MSG = relu(H2 @ W2m + b2m) * mask ; agg = sum over rows(q)
    #pragma unroll
    for (int i = 0; i < 8; i++)
        #pragma unroll
        for (int j = 0; j < 8; j++) acc[i][j] = 0.f;
    gemm_tile(sH, sW, W2m, 128, 256, tid, row0, col0, acc);
    {
        float bj[8], csum[8];
        #pragma unroll
        for (int j = 0; j < 8; j++) { bj[j] = b2m[col0 + j]; csum[j] = 0.f; }
        #pragma unroll
        for (int i = 0; i < 8; i++) {
            float mv = sMask[row0 + i];
            #pragma unroll
            for (int j = 0; j < 8; j++)
                csum[j] += fmaxf(acc[i][j] + bj[j], 0.f) * mv;
        }
        __syncthreads();  // all GEMM4 reads of sW done before aliasing as sRed
        #pragma unroll
        for (int j = 0; j < 8; j++)
            sRed[ty * 128 + col0 + j] = csum[j];
        __syncthreads();
        if (tid < 128) {
            float s = 0.f;
            #pragma unroll
            for (int t = 0; t < 16; t++) s += sRed[t * 128 + tid];
            g_agg[((size_t)bb * 128 + p) * 128 + tid] = s;
        }
    }
}

// ---------------------------------------------------------------------------
// Kernel C: node update + BN. Block = 16 node rows.
// ---------------------------------------------------------------------------
__global__ __launch_bounds__(256) void node_kernel(
    const float* __restrict__ W1u, const float* __restrict__ b1u,
    const float* __restrict__ W2u, const float* __restrict__ b2u,
    const float* __restrict__ gamma_n, const float* __restrict__ beta_n,
    const float* __restrict__ mean_n,  const float* __restrict__ var_n,
    float* __restrict__ nodes_out)
{
    __shared__ float sA[16 * 128];
    __shared__ float sH2[16 * 256];
    int row0 = blockIdx.x * 16;
    int tid = threadIdx.x;

    for (int idx = tid; idx < 2048; idx += 256)
        sA[idx] = g_agg[(size_t)row0 * 128 + idx];
    __syncthreads();

    // phase 1: h[r][col] over 256 cols (col = tid)
    {
        float a[16];
        #pragma unroll
        for (int r = 0; r < 16; r++) a[r] = 0.f;
        const float* W = W1u + (size_t)128 * 256 + tid;
        #pragma unroll 2
        for (int kb = 0; kb < 128; kb += 4) {
            float w0 = W[(size_t)(kb + 0) * 256];
            float w1 = W[(size_t)(kb + 1) * 256];
            float w2 = W[(size_t)(kb + 2) * 256];
            float w3 = W[(size_t)(kb + 3) * 256];
            #pragma unroll
            for (int r = 0; r < 16; r++) {
                float4 xv = *(const float4*)(sA + r * 128 + kb);
                a[r] += xv.x * w0 + xv.y * w1 + xv.z * w2 + xv.w * w3;
            }
        }
        float bb1 = b1u[tid];
        #pragma unroll
        for (int r = 0; r < 16; r++) {
            float v = a[r] + g_Pu[(size_t)(row0 + r) * 256 + tid] + bb1;
            sH2[r * 256 + tid] = fmaxf(v, 0.f);
        }
    }
    __syncthreads();

    // phase 2: s[r][col] over 128 cols; thread handles 8 rows
    {
        int col = tid & 127;
        int rh  = tid >> 7;   // 0 or 1 -> rows rh*8 .. rh*8+7
        float c8[8];
        #pragma unroll
        for (int rr = 0; rr < 8; rr++) c8[rr] = 0.f;
        const float* W2 = W2u + col;
        #pragma unroll 2
        for (int kb = 0; kb < 256; kb += 4) {
            float w0 = W2[(size_t)(kb + 0) * 128];
            float w1 = W2[(size_t)(kb + 1) * 128];
            float w2 = W2[(size_t)(kb + 2) * 128];
            float w3 = W2[(size_t)(kb + 3) * 128];
            #pragma unroll
            for (int rr = 0; rr < 8; rr++) {
                float4 hv = *(const float4*)(sH2 + (rh * 8 + rr) * 256 + kb);
                c8[rr] += hv.x * w0 + hv.y * w1 + hv.z * w2 + hv.w * w3;
            }
        }
        float bb2 = b2u[col];
        float s = gamma_n[col] * rsqrtf(var_n[col] + EPSBN);
        float sh = beta_n[col] - mean_n[col] * s;
        #pragma unroll
        for (int rr = 0; rr < 8; rr++) {
            float v = fmaxf(c8[rr] + bb2, 0.f);
            nodes_out[(size_t)(row0 + rh * 8 + rr) * 128 + col] = v * s + sh;
        }
    }
}

// ---------------------------------------------------------------------------
extern "C" void kernel_launch(void* const* d_in, const int* in_sizes, int n_in,
                              void* d_out, int out_size)
{
    const float* nodes = (const float*)d_in[0];
    const float* edges = (const float*)d_in[1];
    const float* mask  = (const float*)d_in[2];
    const float* W1a = (const float*)d_in[3];
    const float* b1a = (const float*)d_in[4];
    const float* W2a = (const float*)d_in[5];
    const float* b2a = (const float*)d_in[6];
    const float* W1m = (const float*)d_in[7];
    const float* b1m = (const float*)d_in[8];
    const float* W2m = (const float*)d_in[9];
    const float* b2m = (const float*)d_in[10];
    const float* W1u = (const float*)d_in[11];
    const float* b1u = (const float*)d_in[12];
    const float* W2u = (const float*)d_in[13];
    const float* b2u = (const float*)d_in[14];
    const float* gamma_n = (const float*)d_in[15];
    const float* beta_n  = (const float*)d_in[16];
    const float* mean_n  = (const float*)d_in[17];
    const float* var_n   = (const float*)d_in[18];
    const float* gamma_e = (const float*)d_in[19];
    const float* beta_e  = (const float*)d_in[20];
    const float* mean_e  = (const float*)d_in[21];
    const float* var_e   = (const float*)d_in[22];

    float* out = (float*)d_out;
    float* nodes_out = out;                      // (16, 128, 128)
    float* edges_out = out + (size_t)Bb * Nn * Dd;  // (16, 16384, 128)

    static const size_t smemB = SMEM_B_FLOATS * sizeof(float);
    cudaFuncSetAttribute(edge_kernel, cudaFuncAttributeMaxDynamicSharedMemorySize,
                         (int)smemB);

    precompute_kernel<<<128, 256>>>(nodes, W1a, W1m, W1u);

    dim3 gridB(Nn, Bb);
    edge_kernel<<<gridB, 256, smemB>>>(edges, mask,
                                       W1a, b1a, W2a, b2a,
                                       W1m, b1m, W2m, b2m,
                                       gamma_e, beta_e, mean_e, var_e,
                                       edges_out);

    node_kernel<<<128, 256>>>(W1u, b1u, W2u, b2u,
                              gamma_n, beta_n, mean_n, var_n,
                              nodes_out);
}

// round 5
// speedup vs baseline: 3.0669x; 3.0669x over previous
#include <cuda_runtime.h>
#include <cuda_fp16.h>
#include <cstdint>
#include <math.h>

#define EPSBN 1e-3f

// ---------------- device scratch (no allocation allowed) ----------------
__device__ __align__(16) float  g_Pj_a[2048 * 256];
__device__ __align__(16) float  g_Pj_m[2048 * 256];
__device__ __align__(16) float  g_Pu [2048 * 256];
__device__ __align__(16) float  g_agg[2048 * 128];
// 6 slabs x [n=128][k=256] fp16  (B[n][k] = W[k][n] pre-transposed)
__device__ __align__(16) __half g_WT[6 * 128 * 256];

// ---------------- PTX helpers (baseline sm_80+, safe for sm_103) --------
__device__ __forceinline__ uint32_t smem_u32(const void* p) {
    uint32_t a;
    asm("{ .reg .u64 t; cvta.to.shared.u64 t, %1; cvt.u32.u64 %0, t; }" : "=r"(a) : "l"(p));
    return a;
}
__device__ __forceinline__ void cp16(uint32_t s, const void* g) {
    asm volatile("cp.async.cg.shared.global [%0], [%1], 16;" :: "r"(s), "l"(g));
}
#define CP_COMMIT() asm volatile("cp.async.commit_group;" ::: "memory")
#define CP_WAIT0()  asm volatile("cp.async.wait_group 0;" ::: "memory")
#define CP_WAIT1()  asm volatile("cp.async.wait_group 1;" ::: "memory")

__device__ __forceinline__ void ldsm4(uint32_t& r0, uint32_t& r1, uint32_t& r2, uint32_t& r3,
                                      uint32_t addr) {
    asm volatile("ldmatrix.sync.aligned.m8n8.x4.shared.b16 {%0,%1,%2,%3}, [%4];"
                 : "=r"(r0), "=r"(r1), "=r"(r2), "=r"(r3) : "r"(addr));
}
__device__ __forceinline__ void mma16816(float* c, const uint32_t* a, uint32_t b0, uint32_t b1) {
    asm volatile("mma.sync.aligned.m16n8k16.row.col.f32.f16.f16.f32 "
                 "{%0,%1,%2,%3},{%4,%5,%6,%7},{%8,%9},{%0,%1,%2,%3};"
                 : "+f"(c[0]), "+f"(c[1]), "+f"(c[2]), "+f"(c[3])
                 : "r"(a[0]), "r"(a[1]), "r"(a[2]), "r"(a[3]), "r"(b0), "r"(b1));
}

// ---------------- SMEM layout (bytes) ----------------
// sA / sH: 128 rows x (256 data + 8 pad) fp16
#define LDA      264
#define OFF_A    0u
#define OFF_H    67584u
#define OFF_B    135168u     // 2 buffers x 128 n x 40 f16
#define BUFSTR   10240u
#define LDB      40
#define OFF_BIAS 155648u     // 128 f32
#define OFF_MASK 156672u     // 128 f32
#define OFF_SCL  157184u
#define OFF_SHF  157696u
#define OFF_RED  158208u     // 4 x 128 f32
#define SMEM_EDGE_BYTES 160256u

// ---------------------------------------------------------------------------
// prep: blocks 0..383 -> Pj_a/Pj_m/Pu ; blocks 384..407 -> g_WT (transpose+f16)
// ---------------------------------------------------------------------------
__global__ __launch_bounds__(256) void prep_kernel(
    const float* __restrict__ nodes,
    const float* __restrict__ W1a, const float* __restrict__ W2a,
    const float* __restrict__ W1m, const float* __restrict__ W2m,
    const float* __restrict__ W1u)
{
    int blk = blockIdx.x, tid = threadIdx.x;
    if (blk < 384) {
        __shared__ float sX[2048];
        int m = blk >> 7, row0 = (blk & 127) * 16;
        for (int i = tid; i < 2048; i += 256) sX[i] = nodes[(size_t)row0 * 128 + i];
        __syncthreads();
        const float* W = (m == 0 ? W1a + 128 * 256 : m == 1 ? W1m + 128 * 256 : W1u) + tid;
        float* O = (m == 0 ? g_Pj_a : m == 1 ? g_Pj_m : g_Pu) + (size_t)row0 * 256 + tid;
        float a[16];
        #pragma unroll
        for (int r = 0; r < 16; r++) a[r] = 0.f;
        #pragma unroll 2
        for (int kb = 0; kb < 128; kb += 4) {
            float w0 = W[(size_t)(kb + 0) * 256];
            float w1 = W[(size_t)(kb + 1) * 256];
            float w2 = W[(size_t)(kb + 2) * 256];
            float w3 = W[(size_t)(kb + 3) * 256];
            #pragma unroll
            for (int r = 0; r < 16; r++) {
                float4 xv = *(const float4*)(sX + r * 128 + kb);
                a[r] += xv.x * w0 + xv.y * w1 + xv.z * w2 + xv.w * w3;
            }
        }
        #pragma unroll
        for (int r = 0; r < 16; r++) O[(size_t)r * 256] = a[r];
        return;
    }
    // weight slabs: slab = c>>2 ; n-part = (c&3)*32 (32 n-rows x 256 k)
    int c = blk - 384;
    int slab = c >> 2;
    int npart = (c & 3) * 32;
    for (int e = tid; e < 8192; e += 256) {
        int n = npart + (e >> 8);
        int k = e & 255;
        float v;
        if (slab == 0 || slab == 1) {
            int col = n + (slab == 1 ? 128 : 0);
            v = (k < 128) ? W1a[(size_t)(256 + k) * 256 + col]
                          : W1a[(size_t)(k - 128) * 256 + col];
        } else if (slab == 2) {
            v = W2a[(size_t)k * 128 + n];
        } else if (slab == 3 || slab == 4) {
            int col = n + (slab == 4 ? 128 : 0);
            v = (k < 128) ? W1m[(size_t)(256 + k) * 256 + col]
                          : W1m[(size_t)(k - 128) * 256 + col];
        } else {
            v = W2m[(size_t)k * 128 + n];
        }
        g_WT[((size_t)slab * 128 + n) * 256 + k] = __float2half_rn(v);
    }
}

// ---------------------------------------------------------------------------
// edge kernel: one (b,p) tile; 6 HMMA slab GEMMs of 128x128x256
// ---------------------------------------------------------------------------
__global__ __launch_bounds__(256, 1) void edge_kernel(
    const float* __restrict__ edges, const float* __restrict__ nodes,
    const float* __restrict__ mask,
    const float* __restrict__ b1a, const float* __restrict__ b2a,
    const float* __restrict__ b1m, const float* __restrict__ b2m,
    const float* __restrict__ gamma_e, const float* __restrict__ beta_e,
    const float* __restrict__ mean_e,  const float* __restrict__ var_e,
    float* __restrict__ edges_out)
{
    extern __shared__ char smc[];
    uint32_t sbase = smem_u32(smc);
    int p = blockIdx.x, bb = blockIdx.y;
    int tid = threadIdx.x, lane = tid & 31, w = tid >> 5;
    int wm = w >> 1, wn = w & 1;
    int m0 = wm * 32, n0 = wn * 64;

    float* sBias = (float*)(smc + OFF_BIAS);
    float* sMask = (float*)(smc + OFF_MASK);
    float* sScl  = (float*)(smc + OFF_SCL);
    float* sShf  = (float*)(smc + OFF_SHF);
    float* sRed  = (float*)(smc + OFF_RED);

    // ldmatrix per-lane offsets
    int aRow = lane & 15;
    int aK   = (lane & 16) ? 8 : 0;
    int bRow = (lane & 7) + ((lane & 16) ? 8 : 0);
    int bK   = (lane & 8) ? 8 : 0;
    int tq = lane >> 2;          // 0..7
    int tc = (lane & 3) * 2;     // col pair base

    // ---- load E (cols 0-127) + nodes_b (cols 128-255) as f16 into sA; consts
    {
        const float4* Eg = (const float4*)(edges + (size_t)(bb * 16384 + p * 128) * 128);
        const float4* Ng = (const float4*)(nodes + (size_t)bb * 16384);
        #pragma unroll 4
        for (int i = tid; i < 4096; i += 256) {
            int qq = i >> 5, k4 = (i & 31) << 2;
            float4 e = __ldg(Eg + i);
            __half2 e0 = __floats2half2_rn(e.x, e.y), e1 = __floats2half2_rn(e.z, e.w);
            *(uint2*)(smc + OFF_A + (size_t)((qq * LDA + k4) << 1)) =
                make_uint2(*(uint32_t*)&e0, *(uint32_t*)&e1);
            float4 nv = __ldg(Ng + i);
            __half2 n0h = __floats2half2_rn(nv.x, nv.y), n1h = __floats2half2_rn(nv.z, nv.w);
            *(uint2*)(smc + OFF_A + (size_t)((qq * LDA + 128 + k4) << 1)) =
                make_uint2(*(uint32_t*)&n0h, *(uint32_t*)&n1h);
        }
        if (tid < 128) {
            sMask[tid] = __ldg(mask + (size_t)bb * 16384 + p * 128 + tid);
            float s = __ldg(gamma_e + tid) * rsqrtf(__ldg(var_e + tid) + EPSBN);
            sScl[tid] = s;
            sShf[tid] = __ldg(beta_e + tid) - __ldg(mean_e + tid) * s;
        }
    }

    const size_t tb = (size_t)(bb * 128 + p) * 256;
    float acc[2][8][4];

    #pragma unroll 1
    for (int g = 0; g < 6; g++) {
        __syncthreads();   // previous epilogue done before sBias overwrite / buffer reads
        if (tid < 128) {
            float bz;
            if      (g == 0) bz = __ldg(b1a + tid)       + g_Pj_a[tb + tid];
            else if (g == 1) bz = __ldg(b1a + 128 + tid) + g_Pj_a[tb + 128 + tid];
            else if (g == 2) bz = __ldg(b2a + tid);
            else if (g == 3) bz = __ldg(b1m + tid)       + g_Pj_m[tb + tid];
            else if (g == 4) bz = __ldg(b1m + 128 + tid) + g_Pj_m[tb + 128 + tid];
            else             bz = __ldg(b2m + tid);
            sBias[tid] = bz;
        }

        uint32_t aOff = (g == 2 || g == 5) ? OFF_H : OFF_A;
        const __half* wsrc = g_WT + (size_t)g * 128 * 256;

        #pragma unroll
        for (int mt = 0; mt < 2; mt++)
            #pragma unroll
            for (int nt = 0; nt < 8; nt++)
                #pragma unroll
                for (int i = 0; i < 4; i++) acc[mt][nt][i] = 0.f;

        // prefetch chunk 0
        #pragma unroll
        for (int j = 0; j < 2; j++) {
            int f = tid + j * 256;
            int n = f >> 2, sub = f & 3;
            cp16(sbase + OFF_B + (uint32_t)(n * LDB * 2 + sub * 16),
                 wsrc + (size_t)n * 256 + sub * 8);
        }
        CP_COMMIT();

        #pragma unroll 1
        for (int c = 0; c < 8; c++) {
            if (c < 7) {
                int kb2 = (c + 1) * 32;
                uint32_t bo = OFF_B + ((c + 1) & 1) * BUFSTR;
                #pragma unroll
                for (int j = 0; j < 2; j++) {
                    int f = tid + j * 256;
                    int n = f >> 2, sub = f & 3;
                    cp16(sbase + bo + (uint32_t)(n * LDB * 2 + sub * 16),
                         wsrc + (size_t)n * 256 + kb2 + sub * 8);
                }
                CP_COMMIT();
                CP_WAIT1();
            } else {
                CP_WAIT0();
            }
            __syncthreads();

            uint32_t bBuf = OFF_B + (c & 1) * BUFSTR;
            int kb = c * 32;
            #pragma unroll
            for (int kt = 0; kt < 2; kt++) {
                int kg = kb + kt * 16;
                uint32_t a0[4], a1[4], bf[16];
                ldsm4(a0[0], a0[1], a0[2], a0[3],
                      sbase + aOff + (uint32_t)(((m0 + aRow) * LDA + kg + aK) << 1));
                ldsm4(a1[0], a1[1], a1[2], a1[3],
                      sbase + aOff + (uint32_t)(((m0 + 16 + aRow) * LDA + kg + aK) << 1));
                #pragma unroll
                for (int pp = 0; pp < 4; pp++)
                    ldsm4(bf[pp * 4], bf[pp * 4 + 1], bf[pp * 4 + 2], bf[pp * 4 + 3],
                          sbase + bBuf +
                          (uint32_t)(((n0 + pp * 16 + bRow) * LDB + kt * 16 + bK) << 1));
                #pragma unroll
                for (int nt = 0; nt < 8; nt++) {
                    uint32_t bb0 = bf[(nt >> 1) * 4 + (nt & 1) * 2];
                    uint32_t bb1 = bf[(nt >> 1) * 4 + (nt & 1) * 2 + 1];
                    mma16816(acc[0][nt], a0, bb0, bb1);
                    mma16816(acc[1][nt], a1, bb0, bb1);
                }
            }
            __syncthreads();
        }

        // ---------------- epilogue ----------------
        if (g == 0 || g == 1 || g == 3 || g == 4) {
            int hb = (g == 1 || g == 4) ? 128 : 0;
            #pragma unroll
            for (int mt = 0; mt < 2; mt++) {
                int r1 = m0 + mt * 16 + tq, r2 = r1 + 8;
                #pragma unroll
                for (int nt = 0; nt < 8; nt++) {
                    int cc = n0 + nt * 8 + tc;
                    float bz0 = sBias[cc], bz1 = sBias[cc + 1];
                    float v0 = fmaxf(acc[mt][nt][0] + bz0, 0.f);
                    float v1 = fmaxf(acc[mt][nt][1] + bz1, 0.f);
                    float v2 = fmaxf(acc[mt][nt][2] + bz0, 0.f);
                    float v3 = fmaxf(acc[mt][nt][3] + bz1, 0.f);
                    __half2 h0 = __floats2half2_rn(v0, v1);
                    __half2 h1 = __floats2half2_rn(v2, v3);
                    *(uint32_t*)(smc + OFF_H + (size_t)((r1 * LDA + hb + cc) << 1)) = *(uint32_t*)&h0;
                    *(uint32_t*)(smc + OFF_H + (size_t)((r2 * LDA + hb + cc) << 1)) = *(uint32_t*)&h1;
                }
            }
        } else if (g == 2) {
            float* go = edges_out + ((size_t)bb * 16384 + (size_t)p * 128) * 128;
            #pragma unroll
            for (int mt = 0; mt < 2; mt++) {
                int r1 = m0 + mt * 16 + tq, r2 = r1 + 8;
                float mk1 = sMask[r1], mk2 = sMask[r2];
                #pragma unroll
                for (int nt = 0; nt < 8; nt++) {
                    int cc = n0 + nt * 8 + tc;
                    float bz0 = sBias[cc], bz1 = sBias[cc + 1];
                    float v0 = fmaxf(acc[mt][nt][0] + bz0, 0.f) * mk1;
                    float v1 = fmaxf(acc[mt][nt][1] + bz1, 0.f) * mk1;
                    float v2 = fmaxf(acc[mt][nt][2] + bz0, 0.f) * mk2;
                    float v3 = fmaxf(acc[mt][nt][3] + bz1, 0.f) * mk2;
                    float s0 = sScl[cc], s1 = sScl[cc + 1];
                    float f0 = sShf[cc], f1 = sShf[cc + 1];
                    *(float2*)(go + (size_t)r1 * 128 + cc) = make_float2(v0 * s0 + f0, v1 * s1 + f1);
                    *(float2*)(go + (size_t)r2 * 128 + cc) = make_float2(v2 * s0 + f0, v3 * s1 + f1);
                    __half2 h0 = __floats2half2_rn(v0, v1);
                    __half2 h1 = __floats2half2_rn(v2, v3);
                    *(uint32_t*)(smc + OFF_A + (size_t)((r1 * LDA + cc) << 1)) = *(uint32_t*)&h0;
                    *(uint32_t*)(smc + OFF_A + (size_t)((r2 * LDA + cc) << 1)) = *(uint32_t*)&h1;
                }
            }
        } else {  // g == 5 : masked column sums over q
            #pragma unroll
            for (int nt = 0; nt < 8; nt++) {
                int cc = n0 + nt * 8 + tc;
                float bz0 = sBias[cc], bz1 = sBias[cc + 1];
                float s0 = 0.f, s1 = 0.f;
                #pragma unroll
                for (int mt = 0; mt < 2; mt++) {
                    int r1 = m0 + mt * 16 + tq, r2 = r1 + 8;
                    float mk1 = sMask[r1], mk2 = sMask[r2];
                    s0 += fmaxf(acc[mt][nt][0] + bz0, 0.f) * mk1
                        + fmaxf(acc[mt][nt][2] + bz0, 0.f) * mk2;
                    s1 += fmaxf(acc[mt][nt][1] + bz1, 0.f) * mk1
                        + fmaxf(acc[mt][nt][3] + bz1, 0.f) * mk2;
                }
                #pragma unroll
                for (int d = 4; d < 32; d <<= 1) {
                    s0 += __shfl_xor_sync(0xffffffffu, s0, d);
                    s1 += __shfl_xor_sync(0xffffffffu, s1, d);
                }
                if (lane < 4) {
                    sRed[wm * 128 + cc]     = s0;
                    sRed[wm * 128 + cc + 1] = s1;
                }
            }
        }
    }
    __syncthreads();
    if (tid < 128) {
        float s = sRed[tid] + sRed[128 + tid] + sRed[256 + tid] + sRed[384 + tid];
        g_agg[(size_t)(bb * 128 + p) * 128 + tid] = s;
    }
}

// ---------------------------------------------------------------------------
// node update + BN (fp32, tiny)
// ---------------------------------------------------------------------------
__global__ __launch_bounds__(256) void node_kernel(
    const float* __restrict__ W1u, const float* __restrict__ b1u,
    const float* __restrict__ W2u, const float* __restrict__ b2u,
    const float* __restrict__ gamma_n, const float* __restrict__ beta_n,
    const float* __restrict__ mean_n,  const float* __restrict__ var_n,
    float* __restrict__ nodes_out)
{
    __shared__ float sA[16 * 128];
    __shared__ float sH2[16 * 256];
    int row0 = blockIdx.x * 16;
    int tid = threadIdx.x;
    for (int i = tid; i < 2048; i += 256) sA[i] = g_agg[(size_t)row0 * 128 + i];
    __syncthreads();
    {
        float a[16];
        #pragma unroll
        for (int r = 0; r < 16; r++) a[r] = 0.f;
        const float* W = W1u + (size_t)128 * 256 + tid;
        #pragma unroll 2
        for (int kb = 0; kb < 128; kb += 4) {
            float w0 = W[(size_t)(kb + 0) * 256];
            float w1 = W[(size_t)(kb + 1) * 256];
            float w2 = W[(size_t)(kb + 2) * 256];
            float w3 = W[(size_t)(kb + 3) * 256];
            #pragma unroll
            for (int r = 0; r < 16; r++) {
                float4 xv = *(const float4*)(sA + r * 128 + kb);
                a[r] += xv.x * w0 + xv.y * w1 + xv.z * w2 + xv.w * w3;
            }
        }
        float bb1 = b1u[tid];
        #pragma unroll
        for (int r = 0; r < 16; r++) {
            float v = a[r] + g_Pu[(size_t)(row0 + r) * 256 + tid] + bb1;
            sH2[r * 256 + tid] = fmaxf(v, 0.f);
        }
    }
    __syncthreads();
    {
        int col = tid & 127;
        int rh  = tid >> 7;
        float c8[8];
        #pragma unroll
        for (int rr = 0; rr < 8; rr++) c8[rr] = 0.f;
        const float* W2 = W2u + col;
        #pragma unroll 2
        for (int kb = 0; kb < 256; kb += 4) {
            float w0 = W2[(size_t)(kb + 0) * 128];
            float w1 = W2[(size_t)(kb + 1) * 128];
            float w2 = W2[(size_t)(kb + 2) * 128];
            float w3 = W2[(size_t)(kb + 3) * 128];
            #pragma unroll
            for (int rr = 0; rr < 8; rr++) {
                float4 hv = *(const float4*)(sH2 + (rh * 8 + rr) * 256 + kb);
                c8[rr] += hv.x * w0 + hv.y * w1 + hv.z * w2 + hv.w * w3;
            }
        }
        float bb2 = b2u[col];
        float s = gamma_n[col] * rsqrtf(var_n[col] + EPSBN);
        float sh = beta_n[col] - mean_n[col] * s;
        #pragma unroll
        for (int rr = 0; rr < 8; rr++) {
            float v = fmaxf(c8[rr] + bb2, 0.f);
            nodes_out[(size_t)(row0 + rh * 8 + rr) * 128 + col] = v * s + sh;
        }
    }
}

// ---------------------------------------------------------------------------
extern "C" void kernel_launch(void* const* d_in, const int* in_sizes, int n_in,
                              void* d_out, int out_size)
{
    const float* nodes = (const float*)d_in[0];
    const float* edges = (const float*)d_in[1];
    const float* mask  = (const float*)d_in[2];
    const float* W1a = (const float*)d_in[3];
    const float* b1a = (const float*)d_in[4];
    const float* W2a = (const float*)d_in[5];
    const float* b2a = (const float*)d_in[6];
    const float* W1m = (const float*)d_in[7];
    const float* b1m = (const float*)d_in[8];
    const float* W2m = (const float*)d_in[9];
    const float* b2m = (const float*)d_in[10];
    const float* W1u = (const float*)d_in[11];
    const float* b1u = (const float*)d_in[12];
    const float* W2u = (const float*)d_in[13];
    const float* b2u = (const float*)d_in[14];
    const float* gamma_n = (const float*)d_in[15];
    const float* beta_n  = (const float*)d_in[16];
    const float* mean_n  = (const float*)d_in[17];
    const float* var_n   = (const float*)d_in[18];
    const float* gamma_e = (const float*)d_in[19];
    const float* beta_e  = (const float*)d_in[20];
    const float* mean_e  = (const float*)d_in[21];
    const float* var_e   = (const float*)d_in[22];

    float* out = (float*)d_out;
    float* nodes_out = out;
    float* edges_out = out + (size_t)16 * 128 * 128;

    cudaFuncSetAttribute(edge_kernel, cudaFuncAttributeMaxDynamicSharedMemorySize,
                         (int)SMEM_EDGE_BYTES);

    prep_kernel<<<408, 256>>>(nodes, W1a, W2a, W1m, W2m, W1u);

    dim3 gridB(128, 16);
    edge_kernel<<<gridB, 256, SMEM_EDGE_BYTES>>>(edges, nodes, mask,
                                                 b1a, b2a, b1m, b2m,
                                                 gamma_e, beta_e, mean_e, var_e,
                                                 edges_out);

    node_kernel<<<128, 256>>>(W1u, b1u, W2u, b2u,
                              gamma_n, beta_n, mean_n, var_n,
                              nodes_out);
}

// round 6
// speedup vs baseline: 3.9606x; 1.2914x over previous
#include <cuda_runtime.h>
#include <cuda_fp16.h>
#include <cstdint>
#include <math.h>

#define EPSBN 1e-3f

// ---------------- device scratch (no allocation allowed) ----------------
__device__ __align__(16) float  g_Pj_a[2048 * 256];
__device__ __align__(16) float  g_Pj_m[2048 * 256];
__device__ __align__(16) float  g_Pu [2048 * 256];
__device__ __align__(16) float  g_agg[2048 * 128];
// 6 slabs x [n=128][k=256] fp16  (B[n][k] = W[k][n] pre-transposed)
__device__ __align__(16) __half g_WT[6 * 128 * 256];

// ---------------- PTX helpers (baseline sm_80+, safe for sm_103) --------
__device__ __forceinline__ uint32_t smem_u32(const void* p) {
    uint32_t a;
    asm("{ .reg .u64 t; cvta.to.shared.u64 t, %1; cvt.u32.u64 %0, t; }" : "=r"(a) : "l"(p));
    return a;
}
__device__ __forceinline__ void cp16(uint32_t s, const void* g) {
    asm volatile("cp.async.cg.shared.global [%0], [%1], 16;" :: "r"(s), "l"(g));
}
#define CP_COMMIT() asm volatile("cp.async.commit_group;" ::: "memory")
#define CP_WAIT0()  asm volatile("cp.async.wait_group 0;" ::: "memory")

__device__ __forceinline__ void ldsm4(uint32_t& r0, uint32_t& r1, uint32_t& r2, uint32_t& r3,
                                      uint32_t addr) {
    asm volatile("ldmatrix.sync.aligned.m8n8.x4.shared.b16 {%0,%1,%2,%3}, [%4];"
                 : "=r"(r0), "=r"(r1), "=r"(r2), "=r"(r3) : "r"(addr));
}
__device__ __forceinline__ void mma16816(float* c, const uint32_t* a, uint32_t b0, uint32_t b1) {
    asm volatile("mma.sync.aligned.m16n8k16.row.col.f32.f16.f16.f32 "
                 "{%0,%1,%2,%3},{%4,%5,%6,%7},{%8,%9},{%0,%1,%2,%3};"
                 : "+f"(c[0]), "+f"(c[1]), "+f"(c[2]), "+f"(c[3])
                 : "r"(a[0]), "r"(a[1]), "r"(a[2]), "r"(a[3]), "r"(b0), "r"(b1));
}

// ---------------- SMEM layout (bytes) ----------------
// sA / sH / sB: 128 rows x (256 data + 8 pad) fp16, stride 528 B (conflict-free ldsm)
#define LDA      264
#define LDB      264
#define OFF_A    0u
#define OFF_H    67584u
#define OFF_B    135168u     // full 128 x 256 weight slab, padded
#define OFF_BIAS 202752u     // 128 f32
#define OFF_MASK 203264u
#define OFF_SCL  203776u
#define OFF_SHF  204288u
#define OFF_RED  204800u     // 4 x 128 f32
#define SMEM_EDGE_BYTES 206848u

// ---------------------------------------------------------------------------
// prep: blocks 0..383 -> Pj_a/Pj_m/Pu ; blocks 384..407 -> g_WT (transpose+f16)
// ---------------------------------------------------------------------------
__global__ __launch_bounds__(256) void prep_kernel(
    const float* __restrict__ nodes,
    const float* __restrict__ W1a, const float* __restrict__ W2a,
    const float* __restrict__ W1m, const float* __restrict__ W2m,
    const float* __restrict__ W1u)
{
    int blk = blockIdx.x, tid = threadIdx.x;
    if (blk < 384) {
        __shared__ float sX[2048];
        int m = blk >> 7, row0 = (blk & 127) * 16;
        for (int i = tid; i < 2048; i += 256) sX[i] = nodes[(size_t)row0 * 128 + i];
        __syncthreads();
        const float* W = (m == 0 ? W1a + 128 * 256 : m == 1 ? W1m + 128 * 256 : W1u) + tid;
        float* O = (m == 0 ? g_Pj_a : m == 1 ? g_Pj_m : g_Pu) + (size_t)row0 * 256 + tid;
        float a[16];
        #pragma unroll
        for (int r = 0; r < 16; r++) a[r] = 0.f;
        #pragma unroll 2
        for (int kb = 0; kb < 128; kb += 4) {
            float w0 = W[(size_t)(kb + 0) * 256];
            float w1 = W[(size_t)(kb + 1) * 256];
            float w2 = W[(size_t)(kb + 2) * 256];
            float w3 = W[(size_t)(kb + 3) * 256];
            #pragma unroll
            for (int r = 0; r < 16; r++) {
                float4 xv = *(const float4*)(sX + r * 128 + kb);
                a[r] += xv.x * w0 + xv.y * w1 + xv.z * w2 + xv.w * w3;
            }
        }
        #pragma unroll
        for (int r = 0; r < 16; r++) O[(size_t)r * 256] = a[r];
        return;
    }
    // weight slabs: slab = c>>2 ; n-part = (c&3)*32 (32 n-rows x 256 k)
    int c = blk - 384;
    int slab = c >> 2;
    int npart = (c & 3) * 32;
    for (int e = tid; e < 8192; e += 256) {
        int n = npart + (e >> 8);
        int k = e & 255;
        float v;
        if (slab == 0 || slab == 1) {
            int col = n + (slab == 1 ? 128 : 0);
            v = (k < 128) ? W1a[(size_t)(256 + k) * 256 + col]
                          : W1a[(size_t)(k - 128) * 256 + col];
        } else if (slab == 2) {
            v = W2a[(size_t)k * 128 + n];
        } else if (slab == 3 || slab == 4) {
            int col = n + (slab == 4 ? 128 : 0);
            v = (k < 128) ? W1m[(size_t)(256 + k) * 256 + col]
                          : W1m[(size_t)(k - 128) * 256 + col];
        } else {
            v = W2m[(size_t)k * 128 + n];
        }
        g_WT[((size_t)slab * 128 + n) * 256 + k] = __float2half_rn(v);
    }
}

// ---------------------------------------------------------------------------
// edge kernel: one (b,p) tile; 6 HMMA slab GEMMs of 128x128x256,
// full weight slab resident in SMEM -> barrier-free K-loop.
// ---------------------------------------------------------------------------
__device__ __forceinline__ void cp_slab(uint32_t sbase, int g, int tid) {
    const __half* wsrc = g_WT + (size_t)g * 128 * 256;
    #pragma unroll
    for (int i = 0; i < 16; i++) {
        int f = tid + i * 256;
        int n = f >> 5, sub = f & 31;
        cp16(sbase + OFF_B + (uint32_t)(n * (LDB * 2) + sub * 16),
             wsrc + (size_t)n * 256 + sub * 8);
    }
    CP_COMMIT();
}

__global__ __launch_bounds__(256, 1) void edge_kernel(
    const float* __restrict__ edges, const float* __restrict__ nodes,
    const float* __restrict__ mask,
    const float* __restrict__ b1a, const float* __restrict__ b2a,
    const float* __restrict__ b1m, const float* __restrict__ b2m,
    const float* __restrict__ gamma_e, const float* __restrict__ beta_e,
    const float* __restrict__ mean_e,  const float* __restrict__ var_e,
    float* __restrict__ edges_out)
{
    extern __shared__ char smc[];
    uint32_t sbase = smem_u32(smc);
    int p = blockIdx.x, bb = blockIdx.y;
    int tid = threadIdx.x, lane = tid & 31, w = tid >> 5;
    int wm = w >> 1, wn = w & 1;
    int m0 = wm * 32, n0 = wn * 64;

    float* sBias = (float*)(smc + OFF_BIAS);
    float* sMask = (float*)(smc + OFF_MASK);
    float* sScl  = (float*)(smc + OFF_SCL);
    float* sShf  = (float*)(smc + OFF_SHF);
    float* sRed  = (float*)(smc + OFF_RED);

    // ldmatrix per-lane offsets
    int aRow = lane & 15;
    int aK   = (lane & 16) ? 8 : 0;
    int bRow = (lane & 7) + ((lane & 16) ? 8 : 0);
    int bK   = (lane & 8) ? 8 : 0;
    int tq = lane >> 2;          // 0..7
    int tc = (lane & 3) * 2;     // col pair base

    // prefetch weight slab 0 FIRST so it overlaps the edge-tile load
    cp_slab(sbase, 0, tid);

    // ---- load E (cols 0-127) + nodes_b (cols 128-255) as f16 into sA; consts
    {
        const float4* Eg = (const float4*)(edges + (size_t)(bb * 16384 + p * 128) * 128);
        const float4* Ng = (const float4*)(nodes + (size_t)bb * 16384);
        #pragma unroll 4
        for (int i = tid; i < 4096; i += 256) {
            int qq = i >> 5, k4 = (i & 31) << 2;
            float4 e = __ldg(Eg + i);
            __half2 e0 = __floats2half2_rn(e.x, e.y), e1 = __floats2half2_rn(e.z, e.w);
            *(uint2*)(smc + OFF_A + (size_t)((qq * LDA + k4) << 1)) =
                make_uint2(*(uint32_t*)&e0, *(uint32_t*)&e1);
            float4 nv = __ldg(Ng + i);
            __half2 n0h = __floats2half2_rn(nv.x, nv.y), n1h = __floats2half2_rn(nv.z, nv.w);
            *(uint2*)(smc + OFF_A + (size_t)((qq * LDA + 128 + k4) << 1)) =
                make_uint2(*(uint32_t*)&n0h, *(uint32_t*)&n1h);
        }
        if (tid < 128) {
            sMask[tid] = __ldg(mask + (size_t)bb * 16384 + p * 128 + tid);
            float s = __ldg(gamma_e + tid) * rsqrtf(__ldg(var_e + tid) + EPSBN);
            sScl[tid] = s;
            sShf[tid] = __ldg(beta_e + tid) - __ldg(mean_e + tid) * s;
        }
    }

    const size_t tb = (size_t)(bb * 128 + p) * 256;
    float acc[2][8][4];

    #pragma unroll 1
    for (int g = 0; g < 6; g++) {
        CP_WAIT0();        // weight slab g resident (this thread's groups)
        __syncthreads();   // everyone's cp.async + prior epilogue writes visible

        if (tid < 128) {
            float bz;
            if      (g == 0) bz = __ldg(b1a + tid)       + g_Pj_a[tb + tid];
            else if (g == 1) bz = __ldg(b1a + 128 + tid) + g_Pj_a[tb + 128 + tid];
            else if (g == 2) bz = __ldg(b2a + tid);
            else if (g == 3) bz = __ldg(b1m + tid)       + g_Pj_m[tb + tid];
            else if (g == 4) bz = __ldg(b1m + 128 + tid) + g_Pj_m[tb + 128 + tid];
            else             bz = __ldg(b2m + tid);
            sBias[tid] = bz;
        }

        uint32_t aOff = (g == 2 || g == 5) ? OFF_H : OFF_A;

        #pragma unroll
        for (int mt = 0; mt < 2; mt++)
            #pragma unroll
            for (int nt = 0; nt < 8; nt++)
                #pragma unroll
                for (int i = 0; i < 4; i++) acc[mt][nt][i] = 0.f;

        // ---- barrier-free K loop: A and full B slab both resident ----
        #pragma unroll 4
        for (int kt = 0; kt < 16; kt++) {
            int kg = kt * 16;
            uint32_t a0[4], a1[4], bf[16];
            ldsm4(a0[0], a0[1], a0[2], a0[3],
                  sbase + aOff + (uint32_t)(((m0 + aRow) * LDA + kg + aK) << 1));
            ldsm4(a1[0], a1[1], a1[2], a1[3],
                  sbase + aOff + (uint32_t)(((m0 + 16 + aRow) * LDA + kg + aK) << 1));
            #pragma unroll
            for (int pp = 0; pp < 4; pp++)
                ldsm4(bf[pp * 4], bf[pp * 4 + 1], bf[pp * 4 + 2], bf[pp * 4 + 3],
                      sbase + OFF_B +
                      (uint32_t)(((n0 + pp * 16 + bRow) * LDB + kg + bK) << 1));
            #pragma unroll
            for (int nt = 0; nt < 8; nt++) {
                uint32_t bb0 = bf[(nt >> 1) * 4 + (nt & 1) * 2];
                uint32_t bb1 = bf[(nt >> 1) * 4 + (nt & 1) * 2 + 1];
                mma16816(acc[0][nt], a0, bb0, bb1);
                mma16816(acc[1][nt], a1, bb0, bb1);
            }
        }

        __syncthreads();                 // all reads of sB done
        if (g < 5) cp_slab(sbase, g + 1, tid);   // overlap next B load with epilogue

        // ---------------- epilogue ----------------
        if (g == 0 || g == 1 || g == 3 || g == 4) {
            int hb = (g == 1 || g == 4) ? 128 : 0;
            #pragma unroll
            for (int mt = 0; mt < 2; mt++) {
                int r1 = m0 + mt * 16 + tq, r2 = r1 + 8;
                #pragma unroll
                for (int nt = 0; nt < 8; nt++) {
                    int cc = n0 + nt * 8 + tc;
                    float bz0 = sBias[cc], bz1 = sBias[cc + 1];
                    float v0 = fmaxf(acc[mt][nt][0] + bz0, 0.f);
                    float v1 = fmaxf(acc[mt][nt][1] + bz1, 0.f);
                    float v2 = fmaxf(acc[mt][nt][2] + bz0, 0.f);
                    float v3 = fmaxf(acc[mt][nt][3] + bz1, 0.f);
                    __half2 h0 = __floats2half2_rn(v0, v1);
                    __half2 h1 = __floats2half2_rn(v2, v3);
                    *(uint32_t*)(smc + OFF_H + (size_t)((r1 * LDA + hb + cc) << 1)) = *(uint32_t*)&h0;
                    *(uint32_t*)(smc + OFF_H + (size_t)((r2 * LDA + hb + cc) << 1)) = *(uint32_t*)&h1;
                }
            }
        } else if (g == 2) {
            float* go = edges_out + ((size_t)bb * 16384 + (size_t)p * 128) * 128;
            #pragma unroll
            for (int mt = 0; mt < 2; mt++) {
                int r1 = m0 + mt * 16 + tq, r2 = r1 + 8;
                float mk1 = sMask[r1], mk2 = sMask[r2];
                #pragma unroll
                for (int nt = 0; nt < 8; nt++) {
                    int cc = n0 + nt * 8 + tc;
                    float bz0 = sBias[cc], bz1 = sBias[cc + 1];
                    float v0 = fmaxf(acc[mt][nt][0] + bz0, 0.f) * mk1;
                    float v1 = fmaxf(acc[mt][nt][1] + bz1, 0.f) * mk1;
                    float v2 = fmaxf(acc[mt][nt][2] + bz0, 0.f) * mk2;
                    float v3 = fmaxf(acc[mt][nt][3] + bz1, 0.f) * mk2;
                    float s0 = sScl[cc], s1 = sScl[cc + 1];
                    float f0 = sShf[cc], f1 = sShf[cc + 1];
                    *(float2*)(go + (size_t)r1 * 128 + cc) = make_float2(v0 * s0 + f0, v1 * s1 + f1);
                    *(float2*)(go + (size_t)r2 * 128 + cc) = make_float2(v2 * s0 + f0, v3 * s1 + f1);
                    __half2 h0 = __floats2half2_rn(v0, v1);
                    __half2 h1 = __floats2half2_rn(v2, v3);
                    *(uint32_t*)(smc + OFF_A + (size_t)((r1 * LDA + cc) << 1)) = *(uint32_t*)&h0;
                    *(uint32_t*)(smc + OFF_A + (size_t)((r2 * LDA + cc) << 1)) = *(uint32_t*)&h1;
                }
            }
        } else {  // g == 5 : masked column sums over q
            #pragma unroll
            for (int nt = 0; nt < 8; nt++) {
                int cc = n0 + nt * 8 + tc;
                float bz0 = sBias[cc], bz1 = sBias[cc + 1];
                float s0 = 0.f, s1 = 0.f;
                #pragma unroll
                for (int mt = 0; mt < 2; mt++) {
                    int r1 = m0 + mt * 16 + tq, r2 = r1 + 8;
                    float mk1 = sMask[r1], mk2 = sMask[r2];
                    s0 += fmaxf(acc[mt][nt][0] + bz0, 0.f) * mk1
                        + fmaxf(acc[mt][nt][2] + bz0, 0.f) * mk2;
                    s1 += fmaxf(acc[mt][nt][1] + bz1, 0.f) * mk1
                        + fmaxf(acc[mt][nt][3] + bz1, 0.f) * mk2;
                }
                #pragma unroll
                for (int d = 4; d < 32; d <<= 1) {
                    s0 += __shfl_xor_sync(0xffffffffu, s0, d);
                    s1 += __shfl_xor_sync(0xffffffffu, s1, d);
                }
                if (lane < 4) {
                    sRed[wm * 128 + cc]     = s0;
                    sRed[wm * 128 + cc + 1] = s1;
                }
            }
        }
    }
    __syncthreads();
    if (tid < 128) {
        float s = sRed[tid] + sRed[128 + tid] + sRed[256 + tid] + sRed[384 + tid];
        g_agg[(size_t)(bb * 128 + p) * 128 + tid] = s;
    }
}

// ---------------------------------------------------------------------------
// node update + BN (fp32, tiny)
// ---------------------------------------------------------------------------
__global__ __launch_bounds__(256) void node_kernel(
    const float* __restrict__ W1u, const float* __restrict__ b1u,
    const float* __restrict__ W2u, const float* __restrict__ b2u,
    const float* __restrict__ gamma_n, const float* __restrict__ beta_n,
    const float* __restrict__ mean_n,  const float* __restrict__ var_n,
    float* __restrict__ nodes_out)
{
    __shared__ float sA[16 * 128];
    __shared__ float sH2[16 * 256];
    int row0 = blockIdx.x * 16;
    int tid = threadIdx.x;
    for (int i = tid; i < 2048; i += 256) sA[i] = g_agg[(size_t)row0 * 128 + i];
    __syncthreads();
    {
        float a[16];
        #pragma unroll
        for (int r = 0; r < 16; r++) a[r] = 0.f;
        const float* W = W1u + (size_t)128 * 256 + tid;
        #pragma unroll 2
        for (int kb = 0; kb < 128; kb += 4) {
            float w0 = W[(size_t)(kb + 0) * 256];
            float w1 = W[(size_t)(kb + 1) * 256];
            float w2 = W[(size_t)(kb + 2) * 256];
            float w3 = W[(size_t)(kb + 3) * 256];
            #pragma unroll
            for (int r = 0; r < 16; r++) {
                float4 xv = *(const float4*)(sA + r * 128 + kb);
                a[r] += xv.x * w0 + xv.y * w1 + xv.z * w2 + xv.w * w3;
            }
        }
        float bb1 = b1u[tid];
        #pragma unroll
        for (int r = 0; r < 16; r++) {
            float v = a[r] + g_Pu[(size_t)(row0 + r) * 256 + tid] + bb1;
            sH2[r * 256 + tid] = fmaxf(v, 0.f);
        }
    }
    __syncthreads();
    {
        int col = tid & 127;
        int rh  = tid >> 7;
        float c8[8];
        #pragma unroll
        for (int rr = 0; rr < 8; rr++) c8[rr] = 0.f;
        const float* W2 = W2u + col;
        #pragma unroll 2
        for (int kb = 0; kb < 256; kb += 4) {
            float w0 = W2[(size_t)(kb + 0) * 128];
            float w1 = W2[(size_t)(kb + 1) * 128];
            float w2 = W2[(size_t)(kb + 2) * 128];
            float w3 = W2[(size_t)(kb + 3) * 128];
            #pragma unroll
            for (int rr = 0; rr < 8; rr++) {
                float4 hv = *(const float4*)(sH2 + (rh * 8 + rr) * 256 + kb);
                c8[rr] += hv.x * w0 + hv.y * w1 + hv.z * w2 + hv.w * w3;
            }
        }
        float bb2 = b2u[col];
        float s = gamma_n[col] * rsqrtf(var_n[col] + EPSBN);
        float sh = beta_n[col] - mean_n[col] * s;
        #pragma unroll
        for (int rr = 0; rr < 8; rr++) {
            float v = fmaxf(c8[rr] + bb2, 0.f);
            nodes_out[(size_t)(row0 + rh * 8 + rr) * 128 + col] = v * s + sh;
        }
    }
}

// ---------------------------------------------------------------------------
extern "C" void kernel_launch(void* const* d_in, const int* in_sizes, int n_in,
                              void* d_out, int out_size)
{
    const float* nodes = (const float*)d_in[0];
    const float* edges = (const float*)d_in[1];
    const float* mask  = (const float*)d_in[2];
    const float* W1a = (const float*)d_in[3];
    const float* b1a = (const float*)d_in[4];
    const float* W2a = (const float*)d_in[5];
    const float* b2a = (const float*)d_in[6];
    const float* W1m = (const float*)d_in[7];
    const float* b1m = (const float*)d_in[8];
    const float* W2m = (const float*)d_in[9];
    const float* b2m = (const float*)d_in[10];
    const float* W1u = (const float*)d_in[11];
    const float* b1u = (const float*)d_in[12];
    const float* W2u = (const float*)d_in[13];
    const float* b2u = (const float*)d_in[14];
    const float* gamma_n = (const float*)d_in[15];
    const float* beta_n  = (const float*)d_in[16];
    const float* mean_n  = (const float*)d_in[17];
    const float* var_n   = (const float*)d_in[18];
    const float* gamma_e = (const float*)d_in[19];
    const float* beta_e  = (const float*)d_in[20];
    const float* mean_e  = (const float*)d_in[21];
    const float* var_e   = (const float*)d_in[22];

    float* out = (float*)d_out;
    float* nodes_out = out;
    float* edges_out = out + (size_t)16 * 128 * 128;

    cudaFuncSetAttribute(edge_kernel, cudaFuncAttributeMaxDynamicSharedMemorySize,
                         (int)SMEM_EDGE_BYTES);

    prep_kernel<<<408, 256>>>(nodes, W1a, W2a, W1m, W2m, W1u);

    dim3 gridB(128, 16);
    edge_kernel<<<gridB, 256, SMEM_EDGE_BYTES>>>(edges, nodes, mask,
                                                 b1a, b2a, b1m, b2m,
                                                 gamma_e, beta_e, mean_e, var_e,
                                                 edges_out);

    node_kernel<<<128, 256>>>(W1u, b1u, W2u, b2u,
                              gamma_n, beta_n, mean_n, var_n,
                              nodes_out);
}

// round 8
// speedup vs baseline: 4.0304x; 1.0176x over previous
#include <cuda_runtime.h>
#include <cuda_fp16.h>
#include <cstdint>
#include <math.h>

#define EPSBN 1e-3f

// ---------------- device scratch (no allocation allowed) ----------------
__device__ __align__(16) float  g_Pi_a[2048 * 256];
__device__ __align__(16) float  g_Pj_a[2048 * 256];
__device__ __align__(16) float  g_Pi_m[2048 * 256];
__device__ __align__(16) float  g_Pj_m[2048 * 256];
__device__ __align__(16) float  g_Pu [2048 * 256];
__device__ __align__(16) float  g_agg[2048 * 128];
// slabs: g0/g1/g3/g4: [n=128][k=128]; g2/g5: [n=128][k=256]  (B[n][k]=W[k][n])
__device__ __align__(16) __half g_WT[131072];
__constant__ int c_OW[6] = {0, 16384, 32768, 65536, 81920, 98304};  // half offsets

// ---------------- PTX helpers (baseline sm_80+, safe for sm_103) --------
__device__ __forceinline__ uint32_t smem_u32(const void* p) {
    uint32_t a;
    asm("{ .reg .u64 t; cvta.to.shared.u64 t, %1; cvt.u32.u64 %0, t; }" : "=r"(a) : "l"(p));
    return a;
}
__device__ __forceinline__ void cp16(uint32_t s, const void* g) {
    asm volatile("cp.async.cg.shared.global [%0], [%1], 16;" :: "r"(s), "l"(g));
}
#define CP_COMMIT() asm volatile("cp.async.commit_group;" ::: "memory")
#define CP_WAIT0()  asm volatile("cp.async.wait_group 0;" ::: "memory")

__device__ __forceinline__ void ldsm4(uint32_t& r0, uint32_t& r1, uint32_t& r2, uint32_t& r3,
                                      uint32_t addr) {
    asm volatile("ldmatrix.sync.aligned.m8n8.x4.shared.b16 {%0,%1,%2,%3}, [%4];"
                 : "=r"(r0), "=r"(r1), "=r"(r2), "=r"(r3) : "r"(addr));
}
__device__ __forceinline__ void mma16816(float* c, const uint32_t* a, uint32_t b0, uint32_t b1) {
    asm volatile("mma.sync.aligned.m16n8k16.row.col.f32.f16.f16.f32 "
                 "{%0,%1,%2,%3},{%4,%5,%6,%7},{%8,%9},{%0,%1,%2,%3};"
                 : "+f"(c[0]), "+f"(c[1]), "+f"(c[2]), "+f"(c[3])
                 : "r"(a[0]), "r"(a[1]), "r"(a[2]), "r"(a[3]), "r"(b0), "r"(b1));
}

// ---------------- SMEM layout (bytes) ----------------
// sA: 128 x (128+8) f16 (E / NE) ; sH: 128 x (256+8) f16 ; sB: up to 128 x 264 f16
#define LDAE 136
#define LDH  264
#define OFF_A    0u
#define OFF_H    34816u
#define OFF_B    102400u
#define OFF_BIAS 169984u
#define OFF_MASK 170496u
#define OFF_SCL  171008u
#define OFF_SHF  171520u
#define OFF_RED  172032u
#define SMEM_EDGE_BYTES 174080u

// ---------------------------------------------------------------------------
// prep: blocks 0..639 -> Pi_a/Pj_a/Pi_m/Pj_m/Pu ; blocks 640..647 -> g_WT
// ---------------------------------------------------------------------------
__global__ __launch_bounds__(256) void prep_kernel(
    const float* __restrict__ nodes,
    const float* __restrict__ W1a, const float* __restrict__ W2a,
    const float* __restrict__ W1m, const float* __restrict__ W2m,
    const float* __restrict__ W1u)
{
    int blk = blockIdx.x, tid = threadIdx.x;
    if (blk < 640) {
        __shared__ float sX[2048];
        int m = blk >> 7, row0 = (blk & 127) * 16;
        for (int i = tid; i < 2048; i += 256) sX[i] = nodes[(size_t)row0 * 128 + i];
        __syncthreads();
        const float* W;
        float* O;
        switch (m) {
            case 0: W = W1a;             O = g_Pi_a; break;
            case 1: W = W1a + 128 * 256; O = g_Pj_a; break;
            case 2: W = W1m;             O = g_Pi_m; break;
            case 3: W = W1m + 128 * 256; O = g_Pj_m; break;
            default: W = W1u;            O = g_Pu;   break;
        }
        W += tid;
        O += (size_t)row0 * 256 + tid;
        float a[16];
        #pragma unroll
        for (int r = 0; r < 16; r++) a[r] = 0.f;
        #pragma unroll 2
        for (int kb = 0; kb < 128; kb += 4) {
            float w0 = W[(size_t)(kb + 0) * 256];
            float w1 = W[(size_t)(kb + 1) * 256];
            float w2 = W[(size_t)(kb + 2) * 256];
            float w3 = W[(size_t)(kb + 3) * 256];
            #pragma unroll
            for (int r = 0; r < 16; r++) {
                float4 xv = *(const float4*)(sX + r * 128 + kb);
                a[r] += xv.x * w0 + xv.y * w1 + xv.z * w2 + xv.w * w3;
            }
        }
        #pragma unroll
        for (int r = 0; r < 16; r++) O[(size_t)r * 256] = a[r];
        return;
    }
    // weight slabs (transpose + f16)
    int c = blk - 640;  // 0..7
    int slab, nbase;
    if      (c == 0) { slab = 0; nbase = 0; }
    else if (c == 1) { slab = 1; nbase = 0; }
    else if (c <= 3) { slab = 2; nbase = (c - 2) * 64; }
    else if (c == 4) { slab = 3; nbase = 0; }
    else if (c == 5) { slab = 4; nbase = 0; }
    else             { slab = 5; nbase = (c - 6) * 64; }
    int K = (slab == 2 || slab == 5) ? 256 : 128;
    int nrows = (slab == 2 || slab == 5) ? 64 : 128;
    __half* dst = g_WT + c_OW[slab] + (size_t)nbase * K;
    for (int e = tid; e < nrows * K; e += 256) {
        int n = nbase + e / K;
        int k = e % K;
        float v;
        if      (slab == 0) v = W1a[(size_t)(256 + k) * 256 + n];
        else if (slab == 1) v = W1a[(size_t)(256 + k) * 256 + 128 + n];
        else if (slab == 2) v = W2a[(size_t)k * 128 + n];
        else if (slab == 3) v = W1m[(size_t)(256 + k) * 256 + n];
        else if (slab == 4) v = W1m[(size_t)(256 + k) * 256 + 128 + n];
        else                v = W2m[(size_t)k * 128 + n];
        dst[e] = __float2half_rn(v);
    }
}

// ---------------------------------------------------------------------------
// edge kernel helpers
// ---------------------------------------------------------------------------
__device__ __forceinline__ void cp_slab(uint32_t sbase, int g, int tid) {
    const __half* wsrc = g_WT + c_OW[g];
    bool big = (g == 2 || g == 5);
    int sh    = big ? 5 : 4;           // chunks (16B) per row
    int total = big ? 4096 : 2048;
    int ldb2  = big ? (LDH * 2) : (LDAE * 2);
    int K     = big ? 256 : 128;
    for (int f = tid; f < total; f += 256) {
        int n = f >> sh, sub = f & ((1 << sh) - 1);
        cp16(sbase + OFF_B + (uint32_t)(n * ldb2 + sub * 16),
             wsrc + (size_t)n * K + sub * 8);
    }
    CP_COMMIT();
}

template <int KT, int LDA_, int LDB_>
__device__ __forceinline__ void kloop(uint32_t aBase, uint32_t bBase,
                                      int m0, int n0, int aRow, int aK, int bRow, int bK,
                                      float (&acc)[2][8][4])
{
    #pragma unroll 4
    for (int kt = 0; kt < KT; kt++) {
        int kg = kt * 16;
        uint32_t a0[4], a1[4], bf[16];
        ldsm4(a0[0], a0[1], a0[2], a0[3],
              aBase + (uint32_t)(((m0 + aRow) * LDA_ + kg + aK) << 1));
        ldsm4(a1[0], a1[1], a1[2], a1[3],
              aBase + (uint32_t)(((m0 + 16 + aRow) * LDA_ + kg + aK) << 1));
        #pragma unroll
        for (int pp = 0; pp < 4; pp++)
            ldsm4(bf[pp * 4], bf[pp * 4 + 1], bf[pp * 4 + 2], bf[pp * 4 + 3],
                  bBase + (uint32_t)(((n0 + pp * 16 + bRow) * LDB_ + kg + bK) << 1));
        #pragma unroll
        for (int nt = 0; nt < 8; nt++) {
            uint32_t bb0 = bf[(nt >> 1) * 4 + (nt & 1) * 2];
            uint32_t bb1 = bf[(nt >> 1) * 4 + (nt & 1) * 2 + 1];
            mma16816(acc[0][nt], a0, bb0, bb1);
            mma16816(acc[1][nt], a1, bb0, bb1);
        }
    }
}

__global__ __launch_bounds__(256, 1) void edge_kernel(
    const float* __restrict__ edges, const float* __restrict__ mask,
    const float* __restrict__ b1a, const float* __restrict__ b2a,
    const float* __restrict__ b1m, const float* __restrict__ b2m,
    const float* __restrict__ gamma_e, const float* __restrict__ beta_e,
    const float* __restrict__ mean_e,  const float* __restrict__ var_e,
    float* __restrict__ edges_out)
{
    extern __shared__ char smc[];
    uint32_t sbase = smem_u32(smc);
    int p = blockIdx.x, bb = blockIdx.y;
    int tid = threadIdx.x, lane = tid & 31, w = tid >> 5;
    int wm = w >> 1, wn = w & 1;
    int m0 = wm * 32, n0 = wn * 64;

    float* sBias = (float*)(smc + OFF_BIAS);
    float* sMask = (float*)(smc + OFF_MASK);
    float* sScl  = (float*)(smc + OFF_SCL);
    float* sShf  = (float*)(smc + OFF_SHF);
    float* sRed  = (float*)(smc + OFF_RED);

    int aRow = lane & 15;
    int aK   = (lane & 16) ? 8 : 0;
    int bRow = (lane & 7) + ((lane & 16) ? 8 : 0);
    int bK   = (lane & 8) ? 8 : 0;
    int tq = lane >> 2;
    int tc = (lane & 3) * 2;

    cp_slab(sbase, 0, tid);   // prefetch slab 0 (overlaps edge-tile load)

    // ---- load E tile (fp16) + consts
    {
        const float4* Eg = (const float4*)(edges + (size_t)(bb * 16384 + p * 128) * 128);
        #pragma unroll 4
        for (int i = tid; i < 4096; i += 256) {
            int qq = i >> 5, k4 = (i & 31) << 2;
            float4 e = __ldg(Eg + i);
            __half2 e0 = __floats2half2_rn(e.x, e.y), e1 = __floats2half2_rn(e.z, e.w);
            *(uint2*)(smc + OFF_A + (size_t)((qq * LDAE + k4) << 1)) =
                make_uint2(*(uint32_t*)&e0, *(uint32_t*)&e1);
        }
        if (tid < 128) {
            sMask[tid] = __ldg(mask + (size_t)bb * 16384 + p * 128 + tid);
            float s = __ldg(gamma_e + tid) * rsqrtf(__ldg(var_e + tid) + EPSBN);
            sScl[tid] = s;
            sShf[tid] = __ldg(beta_e + tid) - __ldg(mean_e + tid) * s;
        }
    }

    const size_t tb = (size_t)(bb * 128 + p) * 256;
    const size_t pib = (size_t)bb * 128 * 256;   // Pi row base for this batch
    float acc[2][8][4];

    #pragma unroll 1
    for (int g = 0; g < 6; g++) {
        CP_WAIT0();
        __syncthreads();

        if (tid < 128) {
            float bz;
            if      (g == 0) bz = __ldg(b1a + tid)       + g_Pj_a[tb + tid];
            else if (g == 1) bz = __ldg(b1a + 128 + tid) + g_Pj_a[tb + 128 + tid];
            else if (g == 2) bz = __ldg(b2a + tid);
            else if (g == 3) bz = __ldg(b1m + tid)       + g_Pj_m[tb + tid];
            else if (g == 4) bz = __ldg(b1m + 128 + tid) + g_Pj_m[tb + 128 + tid];
            else             bz = __ldg(b2m + tid);
            sBias[tid] = bz;
        }

        #pragma unroll
        for (int mt = 0; mt < 2; mt++)
            #pragma unroll
            for (int nt = 0; nt < 8; nt++)
                #pragma unroll
                for (int i = 0; i < 4; i++) acc[mt][nt][i] = 0.f;

        if (g == 2 || g == 5)
            kloop<16, LDH, LDH>(sbase + OFF_H, sbase + OFF_B,
                                m0, n0, aRow, aK, bRow, bK, acc);
        else
            kloop<8, LDAE, LDAE>(sbase + OFF_A, sbase + OFF_B,
                                 m0, n0, aRow, aK, bRow, bK, acc);

        __syncthreads();
        if (g < 5) cp_slab(sbase, g + 1, tid);   // overlap next B with epilogue

        // ---------------- epilogue ----------------
        if (g == 0 || g == 1 || g == 3 || g == 4) {
            int hb = (g == 1 || g == 4) ? 128 : 0;
            const float* Pi = (g < 2 ? g_Pi_a : g_Pi_m) + pib + hb;
            #pragma unroll
            for (int mt = 0; mt < 2; mt++) {
                int r1 = m0 + mt * 16 + tq, r2 = r1 + 8;
                #pragma unroll
                for (int nt = 0; nt < 8; nt++) {
                    int cc = n0 + nt * 8 + tc;
                    // sBias holds THIS slab's columns compacted at [0..127]
                    float bz0 = sBias[cc], bz1 = sBias[cc + 1];
                    float2 p1 = __ldg((const float2*)(Pi + (size_t)r1 * 256 + cc));
                    float2 p2 = __ldg((const float2*)(Pi + (size_t)r2 * 256 + cc));
                    float v0 = fmaxf(acc[mt][nt][0] + p1.x + bz0, 0.f);
                    float v1 = fmaxf(acc[mt][nt][1] + p1.y + bz1, 0.f);
                    float v2 = fmaxf(acc[mt][nt][2] + p2.x + bz0, 0.f);
                    float v3 = fmaxf(acc[mt][nt][3] + p2.y + bz1, 0.f);
                    __half2 h0 = __floats2half2_rn(v0, v1);
                    __half2 h1 = __floats2half2_rn(v2, v3);
                    *(uint32_t*)(smc + OFF_H + (size_t)((r1 * LDH + hb + cc) << 1)) = *(uint32_t*)&h0;
                    *(uint32_t*)(smc + OFF_H + (size_t)((r2 * LDH + hb + cc) << 1)) = *(uint32_t*)&h1;
                }
            }
        } else if (g == 2) {
            float* go = edges_out + ((size_t)bb * 16384 + (size_t)p * 128) * 128;
            #pragma unroll
            for (int mt = 0; mt < 2; mt++) {
                int r1 = m0 + mt * 16 + tq, r2 = r1 + 8;
                float mk1 = sMask[r1], mk2 = sMask[r2];
                #pragma unroll
                for (int nt = 0; nt < 8; nt++) {
                    int cc = n0 + nt * 8 + tc;
                    float bz0 = sBias[cc], bz1 = sBias[cc + 1];
                    float v0 = fmaxf(acc[mt][nt][0] + bz0, 0.f) * mk1;
                    float v1 = fmaxf(acc[mt][nt][1] + bz1, 0.f) * mk1;
                    float v2 = fmaxf(acc[mt][nt][2] + bz0, 0.f) * mk2;
                    float v3 = fmaxf(acc[mt][nt][3] + bz1, 0.f) * mk2;
                    float s0 = sScl[cc], s1 = sScl[cc + 1];
                    float f0 = sShf[cc], f1 = sShf[cc + 1];
                    *(float2*)(go + (size_t)r1 * 128 + cc) = make_float2(v0 * s0 + f0, v1 * s1 + f1);
                    *(float2*)(go + (size_t)r2 * 128 + cc) = make_float2(v2 * s0 + f0, v3 * s1 + f1);
                    __half2 h0 = __floats2half2_rn(v0, v1);
                    __half2 h1 = __floats2half2_rn(v2, v3);
                    *(uint32_t*)(smc + OFF_A + (size_t)((r1 * LDAE + cc) << 1)) = *(uint32_t*)&h0;
                    *(uint32_t*)(smc + OFF_A + (size_t)((r2 * LDAE + cc) << 1)) = *(uint32_t*)&h1;
                }
            }
        } else {  // g == 5 : masked column sums over q
            #pragma unroll
            for (int nt = 0; nt < 8; nt++) {
                int cc = n0 + nt * 8 + tc;
                float bz0 = sBias[cc], bz1 = sBias[cc + 1];
                float s0 = 0.f, s1 = 0.f;
                #pragma unroll
                for (int mt = 0; mt < 2; mt++) {
                    int r1 = m0 + mt * 16 + tq, r2 = r1 + 8;
                    float mk1 = sMask[r1], mk2 = sMask[r2];
                    s0 += fmaxf(acc[mt][nt][0] + bz0, 0.f) * mk1
                        + fmaxf(acc[mt][nt][2] + bz0, 0.f) * mk2;
                    s1 += fmaxf(acc[mt][nt][1] + bz1, 0.f) * mk1
                        + fmaxf(acc[mt][nt][3] + bz1, 0.f) * mk2;
                }
                #pragma unroll
                for (int d = 4; d < 32; d <<= 1) {
                    s0 += __shfl_xor_sync(0xffffffffu, s0, d);
                    s1 += __shfl_xor_sync(0xffffffffu, s1, d);
                }
                if (lane < 4) {
                    sRed[wm * 128 + cc]     = s0;
                    sRed[wm * 128 + cc + 1] = s1;
                }
            }
        }
    }
    __syncthreads();
    if (tid < 128) {
        float s = sRed[tid] + sRed[128 + tid] + sRed[256 + tid] + sRed[384 + tid];
        g_agg[(size_t)(bb * 128 + p) * 128 + tid] = s;
    }
}

// ---------------------------------------------------------------------------
// node update + BN (fp32, tiny)
// ---------------------------------------------------------------------------
__global__ __launch_bounds__(256) void node_kernel(
    const float* __restrict__ W1u, const float* __restrict__ b1u,
    const float* __restrict__ W2u, const float* __restrict__ b2u,
    const float* __restrict__ gamma_n, const float* __restrict__ beta_n,
    const float* __restrict__ mean_n,  const float* __restrict__ var_n,
    float* __restrict__ nodes_out)
{
    __shared__ float sA[16 * 128];
    __shared__ float sH2[16 * 256];
    int row0 = blockIdx.x * 16;
    int tid = threadIdx.x;
    for (int i = tid; i < 2048; i += 256) sA[i] = g_agg[(size_t)row0 * 128 + i];
    __syncthreads();
    {
        float a[16];
        #pragma unroll
        for (int r = 0; r < 16; r++) a[r] = 0.f;
        const float* W = W1u + (size_t)128 * 256 + tid;
        #pragma unroll 2
        for (int kb = 0; kb < 128; kb += 4) {
            float w0 = W[(size_t)(kb + 0) * 256];
            float w1 = W[(size_t)(kb + 1) * 256];
            float w2 = W[(size_t)(kb + 2) * 256];
            float w3 = W[(size_t)(kb + 3) * 256];
            #pragma unroll
            for (int r = 0; r < 16; r++) {
                float4 xv = *(const float4*)(sA + r * 128 + kb);
                a[r] += xv.x * w0 + xv.y * w1 + xv.z * w2 + xv.w * w3;
            }
        }
        float bb1 = b1u[tid];
        #pragma unroll
        for (int r = 0; r < 16; r++) {
            float v = a[r] + g_Pu[(size_t)(row0 + r) * 256 + tid] + bb1;
            sH2[r * 256 + tid] = fmaxf(v, 0.f);
        }
    }
    __syncthreads();
    {
        int col = tid & 127;
        int rh  = tid >> 7;
        float c8[8];
        #pragma unroll
        for (int rr = 0; rr < 8; rr++) c8[rr] = 0.f;
        const float* W2 = W2u + col;
        #pragma unroll 2
        for (int kb = 0; kb < 256; kb += 4) {
            float w0 = W2[(size_t)(kb + 0) * 128];
            float w1 = W2[(size_t)(kb + 1) * 128];
            float w2 = W2[(size_t)(kb + 2) * 128];
            float w3 = W2[(size_t)(kb + 3) * 128];
            #pragma unroll
            for (int rr = 0; rr < 8; rr++) {
                float4 hv = *(const float4*)(sH2 + (rh * 8 + rr) * 256 + kb);
                c8[rr] += hv.x * w0 + hv.y * w1 + hv.z * w2 + hv.w * w3;
            }
        }
        float bb2 = b2u[col];
        float s = gamma_n[col] * rsqrtf(var_n[col] + EPSBN);
        float sh = beta_n[col] - mean_n[col] * s;
        #pragma unroll
        for (int rr = 0; rr < 8; rr++) {
            float v = fmaxf(c8[rr] + bb2, 0.f);
            nodes_out[(size_t)(row0 + rh * 8 + rr) * 128 + col] = v * s + sh;
        }
    }
}

// ---------------------------------------------------------------------------
extern "C" void kernel_launch(void* const* d_in, const int* in_sizes, int n_in,
                              void* d_out, int out_size)
{
    const float* nodes = (const float*)d_in[0];
    const float* edges = (const float*)d_in[1];
    const float* mask  = (const float*)d_in[2];
    const float* W1a = (const float*)d_in[3];
    const float* b1a = (const float*)d_in[4];
    const float* W2a = (const float*)d_in[5];
    const float* b2a = (const float*)d_in[6];
    const float* W1m = (const float*)d_in[7];
    const float* b1m = (const float*)d_in[8];
    const float* W2m = (const float*)d_in[9];
    const float* b2m = (const float*)d_in[10];
    const float* W1u = (const float*)d_in[11];
    const float* b1u = (const float*)d_in[12];
    const float* W2u = (const float*)d_in[13];
    const float* b2u = (const float*)d_in[14];
    const float* gamma_n = (const float*)d_in[15];
    const float* beta_n  = (const float*)d_in[16];
    const float* mean_n  = (const float*)d_in[17];
    const float* var_n   = (const float*)d_in[18];
    const float* gamma_e = (const float*)d_in[19];
    const float* beta_e  = (const float*)d_in[20];
    const float* mean_e  = (const float*)d_in[21];
    const float* var_e   = (const float*)d_in[22];

    float* out = (float*)d_out;
    float* nodes_out = out;
    float* edges_out = out + (size_t)16 * 128 * 128;

    cudaFuncSetAttribute(edge_kernel, cudaFuncAttributeMaxDynamicSharedMemorySize,
                         (int)SMEM_EDGE_BYTES);

    prep_kernel<<<648, 256>>>(nodes, W1a, W2a, W1m, W2m, W1u);

    dim3 gridB(128, 16);
    edge_kernel<<<gridB, 256, SMEM_EDGE_BYTES>>>(edges, mask,
                                                 b1a, b2a, b1m, b2m,
                                                 gamma_e, beta_e, mean_e, var_e,
                                                 edges_out);

    node_kernel<<<128, 256>>>(W1u, b1u, W2u, b2u,
                              gamma_n, beta_n, mean_n, var_n,
                              nodes_out);
}